// round 17
// baseline (speedup 1.0000x reference)
#include <cuda_runtime.h>
#include <math.h>

// ---------------------------------------------------------------------------
// N=3072 all-pairs mask/bucket kernel.
// Out sections (float32, concatenated): dxyz (N,N,3), buckets (N,N),
// dscanid (N,N), mask (N,N).
//
// R15 -> R16 (on R13 winner: warp owns 128 consecutive j, SIMD byte-packed
// meta compares, smem-staged dxyz, coalesced scalar B/D/M stores):
//   * software-pipelined j loads (depth 2): slice t+1 loads issue before
//     slice t compute -> overlaps long-scoreboard latency (issue was 61%
//     with no pipe saturated => latency-bound)
//   * I2F conversions moved into the rare masked path
// ---------------------------------------------------------------------------

#define MAXN 8192
__device__ float4   g_P[MAXN];   // {x, y, z, cb_as_float}
__device__ unsigned g_X[MAXN];   // xb

// cb bytes: b0=c0, b1=c1, b2=c2, b3=blk
// xb bytes: b0=xc0+16, b1=xc1+16, b2=batch, b3=0
__global__ void pack_kernel(const float* __restrict__ xyz,
                            const int*   __restrict__ grid, int N) {
    int i = blockIdx.x * blockDim.x + threadIdx.x;
    if (i >= N) return;
    float x = xyz[3*i+0], y = xyz[3*i+1], z = xyz[3*i+2];
    int batch = grid[5*i+0], blk = grid[5*i+1];
    int c0 = grid[5*i+2], c1 = grid[5*i+3], c2 = grid[5*i+4];
    // xy_coarse = ceil(xyz[:, :2] / 3.0)  — pinned IEEE division
    int xc0 = (int)ceilf(__fdiv_rn(x, 3.0f));
    int xc1 = (int)ceilf(__fdiv_rn(y, 3.0f));
    unsigned cb = (unsigned)(c0 & 0xFF)
                | ((unsigned)(c1 & 0xFF) << 8)
                | ((unsigned)(c2 & 0xFF) << 16)
                | ((unsigned)(blk & 0xFF) << 24);
    unsigned xb = (unsigned)((xc0 + 16) & 0xFF)
                | ((unsigned)((xc1 + 16) & 0xFF) << 8)
                | ((unsigned)(batch & 0xFF) << 16);
    g_P[i] = make_float4(x, y, z, __uint_as_float(cb));
    g_X[i] = xb;
}

// bucket_base minus BETA: integer-valued float v, reference value = 8 + v.
__device__ __forceinline__ float bucket_v(float d) {
    float x  = d * 2.0f;            // x / RES, RES = 0.5 (exact)
    float xa = fabsf(x);
    if (xa <= 2.0f) {
        return rintf(x);            // round-half-even == jnp.round
    } else {
        float lr  = logf(xa * 0.5f) * 0.48089834696298783f; // 1/ln(8)
        float sup = fminf(rintf(2.0f - 6.0f * lr), 8.0f);
        return (x > 0.0f) ? sup : -sup;
    }
}

__global__ __launch_bounds__(256)
void pair_kernel(float* __restrict__ out, int N) {
    __shared__ float sdx[8][384];      // per-warp dxyz staging (1.5 KB each)

    int warp = threadIdx.x >> 5;
    int lane = threadIdx.x & 31;
    int i    = blockIdx.y;
    int j0w  = blockIdx.x * 1024 + warp * 128;   // warp's 128-wide j base
    if (j0w >= N) return;
    bool full = (j0w + 128 <= N);

    float4 pi = g_P[i];
    unsigned cbi = __float_as_uint(pi.w);
    unsigned xbi = g_X[i];
    int bi = (int)(cbi >> 24);
    int si = bi >> 1;   // scanid_i

    size_t NN   = (size_t)N * (size_t)N;
    size_t rowb = (size_t)i * (size_t)N + (size_t)j0w;
    float* outB = out + 3*NN + rowb;   // buckets row base
    float* outD = out + 4*NN + rowb;   // dscanid row base
    float* outM = out + 5*NN + rowb;   // mask row base
    float* sw   = &sdx[warp][lane * 3];

    if (full) {
        // software pipeline: slice t+1 loads in flight during slice t compute
        float4   pjn = g_P[j0w + lane];
        unsigned xbn = g_X[j0w + lane];
#pragma unroll
        for (int t = 0; t < 4; t++) {
            float4   pj  = pjn;
            unsigned xbj = xbn;
            if (t < 3) {
                pjn = g_P[j0w + (t+1)*32 + lane];
                xbn = g_X[j0w + (t+1)*32 + lane];
            }
            unsigned cbj = __float_as_uint(pj.w);

            // forcekeep: coord bytes absdiff<=1, blk byte diff==0
            unsigned v1 = __vcmpleu4(__vabsdiffu4(cbi, cbj), 0x00010101u);
            bool forcekeep = (v1 == 0xFFFFFFFFu);
            // v2: bytes0,1 coarse-adj, byte2 batch-eq, byte3 trivially true
            unsigned v2 = __vcmpleu4(__vabsdiffu4(xbi, xbj), 0x00000101u);
            bool kc_batch = (v2 == 0xFFFFFFFFu);     // batch_eq & keep_coarse
            bool batch_eq = (v2 & 0x00FF0000u) != 0u;

            int  bj       = (int)(cbj >> 24);
            bool block_le = (bi <= bj);

            float dx = pi.x - pj.x, dy = pi.y - pj.y, dz = pi.z - pj.z;
            bool keepr = (dx*dx + dy*dy + dz*dz) <= 9.0f;

            // == batch_eq & block_le & (fk|kc) & (fk|keepr)
            bool mask = block_le & ((forcekeep & batch_eq) | (kc_batch & keepr));

            sw[t*96 + 0] = mask ? dx : 0.0f;
            sw[t*96 + 1] = mask ? dy : 0.0f;
            sw[t*96 + 2] = mask ? dz : 0.0f;

            // sparse + warp-coherent: divergent bucket path wins;
            // I2F also only paid when masked
            float fb = 0.0f, fds = 0.0f;
            if (mask) {
                int b = 289 * (8 + (int)bucket_v(dx))
                      +  17 * (8 + (int)bucket_v(dy))
                      +        (8 + (int)bucket_v(dz));
                fb  = (float)b;
                fds = (float)((bj >> 1) - si);
            }
            int jl = t * 32 + lane;
            outB[jl] = fb;
            outD[jl] = fds;
            outM[jl] = mask ? 1.0f : 0.0f;
        }

        __syncwarp();

        // dxyz: 384 consecutive floats per warp -> 3 contiguous float4 bursts
        const float4* src = reinterpret_cast<const float4*>(sdx[warp]);
        float4* dst = reinterpret_cast<float4*>(out + rowb * 3);
        dst[lane]      = src[lane];
        dst[lane + 32] = src[lane + 32];
        dst[lane + 64] = src[lane + 64];
    } else {
        // generic tail path (not taken at N=3072)
#pragma unroll
        for (int t = 0; t < 4; t++) {
            int jl = t * 32 + lane;
            int j  = j0w + jl;
            bool inb = (j < N);
            float4   pj  = g_P[inb ? j : 0];
            unsigned cbj = __float_as_uint(pj.w);
            unsigned xbj = g_X[inb ? j : 0];

            unsigned v1 = __vcmpleu4(__vabsdiffu4(cbi, cbj), 0x00010101u);
            bool forcekeep = (v1 == 0xFFFFFFFFu);
            unsigned v2 = __vcmpleu4(__vabsdiffu4(xbi, xbj), 0x00000101u);
            bool kc_batch = (v2 == 0xFFFFFFFFu);
            bool batch_eq = (v2 & 0x00FF0000u) != 0u;

            int  bj       = (int)(cbj >> 24);
            bool block_le = (bi <= bj);

            float dx = pi.x - pj.x, dy = pi.y - pj.y, dz = pi.z - pj.z;
            bool keepr = (dx*dx + dy*dy + dz*dz) <= 9.0f;

            bool mask = block_le & ((forcekeep & batch_eq) | (kc_batch & keepr)) & inb;

            sw[t*96 + 0] = mask ? dx : 0.0f;
            sw[t*96 + 1] = mask ? dy : 0.0f;
            sw[t*96 + 2] = mask ? dz : 0.0f;

            float fb = 0.0f, fds = 0.0f;
            if (mask) {
                int b = 289 * (8 + (int)bucket_v(dx))
                      +  17 * (8 + (int)bucket_v(dy))
                      +        (8 + (int)bucket_v(dz));
                fb  = (float)b;
                fds = (float)((bj >> 1) - si);
            }
            if (inb) {
                outB[jl] = fb;
                outD[jl] = fds;
                outM[jl] = mask ? 1.0f : 0.0f;
            }
        }

        __syncwarp();

        int nrem = (N - j0w) * 3;      // floats in this partial tile
        for (int k = lane; k < nrem; k += 32)
            out[rowb * 3 + k] = sdx[warp][k];
    }
}

extern "C" void kernel_launch(void* const* d_in, const int* in_sizes, int n_in,
                              void* d_out, int out_size) {
    const float* xyz  = (const float*)d_in[0];
    const int*   grid = (const int*)d_in[1];
    int N = in_sizes[0] / 3;
    float* out = (float*)d_out;

    pack_kernel<<<(N + 255) / 256, 256>>>(xyz, grid, N);

    dim3 g((N + 1023) / 1024, N);
    pair_kernel<<<g, 256>>>(out, N);
}